// round 4
// baseline (speedup 1.0000x reference)
#include <cuda_runtime.h>

// Problem: x[128,3,16,64,64] (*) w[24,3,3,3,3] VALID -> +bias -> min over depth(14) -> softmax over 24 ch
// out: [128,24,62,62] fp32

#define THREADS 192
#define NOC 8  // output channels per thread (3 "thirds" x 8 = 24)

typedef unsigned long long ull;

__device__ __forceinline__ ull ffma2(ull a, ull b, ull c) {
    ull d;
    asm("fma.rn.f32x2 %0, %1, %2, %3;" : "=l"(d) : "l"(a), "l"(b), "l"(c));
    return d;
}

__device__ __forceinline__ ull min2(ull a, ull b) {
    float alo = __uint_as_float((unsigned)a);
    float ahi = __uint_as_float((unsigned)(a >> 32));
    float blo = __uint_as_float((unsigned)b);
    float bhi = __uint_as_float((unsigned)(b >> 32));
    float lo = fminf(alo, blo), hi = fminf(ahi, bhi);
    return ((ull)__float_as_uint(hi) << 32) | (ull)__float_as_uint(lo);
}

// shared layout (floats):
//   wsm    [27][24][8]   : 5184   duplicated weight pairs, kw padded to 4 pairs
//   bdup   [24][2]       : 48     duplicated bias pairs
//   ring   [4][2592]     : 10368  per slot: sA[3*6][72] then sB[3*6][72] (sB = shifted by +1)
//   minbuf [24][256]     : 6144
#define SM_WSM    0
#define SM_BDUP   5184
#define SM_RING   5232
#define SM_MINBUF 15600
#define SM_TOTAL  21744   // floats -> 86976 bytes

__global__ __launch_bounds__(THREADS, 2)
void conv3d_min_softmax_kernel(const float* __restrict__ x,
                               const float* __restrict__ wgt,
                               const float* __restrict__ bias,
                               float* __restrict__ out)
{
    extern __shared__ float smem[];
    float* wsm    = smem + SM_WSM;
    float* bdup   = smem + SM_BDUP;
    float* ring   = smem + SM_RING;
    float* minbuf = smem + SM_MINBUF;

    const int tid = threadIdx.x;
    const int b   = blockIdx.y;       // 0..127
    const int r0  = blockIdx.x * 4;   // output row tile base, 0..60

    // ---- stage weights (duplicated f32x2 pairs, kw padded to 4) ----
    for (int i = tid; i < 1944; i += THREADS) {
        int oc = i / 81, rem = i % 81;
        int ckk = rem / 3, kw = rem % 3;       // ckk = cin*9 + kd*3 + kh
        float v = wgt[i];
        int idx = (ckk * 24 + oc) * 8 + kw * 2;
        wsm[idx] = v; wsm[idx + 1] = v;
    }
    for (int i = tid; i < 648; i += THREADS) { wsm[i * 8 + 6] = 0.f; wsm[i * 8 + 7] = 0.f; }
    if (tid < 24) { bdup[2 * tid] = bias[tid]; bdup[2 * tid + 1] = bias[tid]; }

    // ---- zero ring pads (cols >= 64 of sA, cols >= 63 of sB) ----
    for (int i = tid; i < 4 * 18; i += THREADS) {
        float* a = ring + (i / 18) * 2592 + (i % 18) * 72;
        #pragma unroll
        for (int c = 64; c < 72; ++c) a[c] = 0.f;
        float* bb = a + 1296;
        #pragma unroll
        for (int c = 63; c < 72; ++c) bb[c] = 0.f;
    }

    const float* xb = x + (size_t)b * (3 * 16 * 4096);

    // ---- prologue: slices 0..2 direct to ring ----
    for (int s = 0; s < 3; ++s) {
        #pragma unroll
        for (int k = 0; k < 6; ++k) {
            int i = tid + k * THREADS;              // 0..1151 (3*6*64)
            int cin = i / 384, rem = i % 384;
            int row = rem >> 6, w = rem & 63;
            int gr = min(r0 + row, 63);
            float v = xb[((cin * 16 + s) << 12) + (gr << 6) + w];
            float* base = ring + s * 2592 + (cin * 6 + row) * 72;
            base[w] = v;
            if (w) base[1296 + w - 1] = v;
        }
    }
    // stage slice 3 into regs
    float stg[6];
    #pragma unroll
    for (int k = 0; k < 6; ++k) {
        int i = tid + k * THREADS;
        int cin = i / 384, rem = i % 384;
        int row = rem >> 6, w = rem & 63;
        int gr = min(r0 + row, 63);
        stg[k] = xb[((cin * 16 + 3) << 12) + (gr << 6) + w];
    }
    __syncthreads();

    const int third = tid / 64;          // 0..2 -> oc range
    const int g     = tid % 64;          // pixel group
    const int r     = g >> 4;            // tile row 0..3
    const int w0    = (g & 15) * 4;      // pixel base 0..60
    const int oc0   = third * NOC;

    const ull INF2 = 0x7F8000007F800000ULL;
    ull mnA[NOC], mnB[NOC];
    #pragma unroll
    for (int j = 0; j < NOC; ++j) { mnA[j] = INF2; mnB[j] = INF2; }

    #pragma unroll 1
    for (int d = 0; d < 14; ++d) {
        ull accA[NOC], accB[NOC];
        #pragma unroll
        for (int j = 0; j < NOC; ++j) {
            ull bj = *reinterpret_cast<const ull*>(bdup + 2 * (oc0 + j));
            accA[j] = bj; accB[j] = bj;
        }

        #pragma unroll
        for (int cin = 0; cin < 3; ++cin) {
            #pragma unroll 1
            for (int kd = 0; kd < 3; ++kd) {
                const float* slot = ring + ((d + kd) & 3) * 2592 + (cin * 6 + r) * 72 + w0;
                #pragma unroll
                for (int kh = 0; kh < 3; ++kh) {
                    const float* rowA = slot + kh * 72;
                    const float* rowB = rowA + 1296;
                    ull p01 = *reinterpret_cast<const ull*>(rowA);
                    ull p23 = *reinterpret_cast<const ull*>(rowA + 2);
                    ull p45 = *reinterpret_cast<const ull*>(rowA + 4);
                    ull p12 = *reinterpret_cast<const ull*>(rowB);
                    ull p34 = *reinterpret_cast<const ull*>(rowB + 2);
                    const float* wp = wsm + ((cin * 9 + kd * 3 + kh) * 24 + oc0) * 8;
                    #pragma unroll
                    for (int j = 0; j < NOC; ++j) {
                        ulonglong2 w01 = *reinterpret_cast<const ulonglong2*>(wp + j * 8);
                        ull w2 = *reinterpret_cast<const ull*>(wp + j * 8 + 4);
                        accA[j] = ffma2(w01.x, p01, accA[j]);
                        accA[j] = ffma2(w01.y, p12, accA[j]);
                        accA[j] = ffma2(w2,    p23, accA[j]);
                        accB[j] = ffma2(w01.x, p23, accB[j]);
                        accB[j] = ffma2(w01.y, p34, accB[j]);
                        accB[j] = ffma2(w2,    p45, accB[j]);
                    }
                }
            }
        }
        #pragma unroll
        for (int j = 0; j < NOC; ++j) {
            mnA[j] = min2(mnA[j], accA[j]);
            mnB[j] = min2(mnB[j], accB[j]);
        }

        __syncthreads();  // everyone done reading slot (d+3)&3 (held slice d-1)
        if (d + 3 <= 15) {
            float* sl = ring + ((d + 3) & 3) * 2592;
            #pragma unroll
            for (int k = 0; k < 6; ++k) {
                int i = tid + k * THREADS;
                int cin = i / 384, rem = i % 384;
                int row = rem >> 6, w = rem & 63;
                float* base = sl + (cin * 6 + row) * 72;
                base[w] = stg[k];
                if (w) base[1296 + w - 1] = stg[k];
            }
        }
        if (d + 4 <= 15) {
            #pragma unroll
            for (int k = 0; k < 6; ++k) {
                int i = tid + k * THREADS;
                int cin = i / 384, rem = i % 384;
                int row = rem >> 6, w = rem & 63;
                int gr = min(r0 + row, 63);
                stg[k] = xb[((cin * 16 + d + 4) << 12) + (gr << 6) + w];
            }
        }
        __syncthreads();
    }

    // ---- exchange per-channel mins via smem ----
    #pragma unroll
    for (int j = 0; j < NOC; ++j) {
        float4 v;
        v.x = __uint_as_float((unsigned)mnA[j]);
        v.y = __uint_as_float((unsigned)(mnA[j] >> 32));
        v.z = __uint_as_float((unsigned)mnB[j]);
        v.w = __uint_as_float((unsigned)(mnB[j] >> 32));
        *reinterpret_cast<float4*>(minbuf + (oc0 + j) * 256 + g * 4) = v;
    }
    __syncthreads();

    // ---- softmax over 24 channels per pixel ----
    for (int p = tid; p < 256; p += THREADS) {
        float m = -3.402823466e38f;
        #pragma unroll
        for (int oc = 0; oc < 24; ++oc) m = fmaxf(m, minbuf[oc * 256 + p]);
        float s = 0.f;
        #pragma unroll
        for (int oc = 0; oc < 24; ++oc) {
            float e = __expf(minbuf[oc * 256 + p] - m);
            minbuf[oc * 256 + p] = e;
            s += e;
        }
        float rinv = 1.0f / s;
        #pragma unroll
        for (int oc = 0; oc < 24; ++oc) minbuf[oc * 256 + p] *= rinv;
    }
    __syncthreads();

    // ---- coalesced store ----
    float* ob = out + (size_t)b * (24 * 62 * 62);
    for (int i = tid; i < 24 * 256; i += THREADS) {
        int oc = i >> 8, rem = i & 255;
        int row = rem >> 6, w = rem & 63;
        int oh = r0 + row;
        if (w < 62 && oh < 62)
            ob[(oc * 62 + oh) * 62 + w] = minbuf[i];
    }
}

extern "C" void kernel_launch(void* const* d_in, const int* in_sizes, int n_in,
                              void* d_out, int out_size) {
    const float* x    = (const float*)d_in[0];
    const float* wgt  = (const float*)d_in[1];
    const float* bias = (const float*)d_in[2];
    float* out = (float*)d_out;

    cudaFuncSetAttribute(conv3d_min_softmax_kernel,
                         cudaFuncAttributeMaxDynamicSharedMemorySize,
                         SM_TOTAL * (int)sizeof(float));
    dim3 grid(16, 128);  // 16 row-tiles x 128 batches
    conv3d_min_softmax_kernel<<<grid, THREADS, SM_TOTAL * sizeof(float)>>>(x, wgt, bias, out);
}